// round 1
// baseline (speedup 1.0000x reference)
#include <cuda_runtime.h>
#include <math.h>

#define BSZ 8
#define CH  1024
#define TT  1024
#define NH  16
#define HD  64
#define RD  32   // rope dim
#define RH  16   // rope half

// ---------------- scratch (device globals; no allocation allowed) ----------
__device__ float g_p[(size_t)BSZ * CH * TT];   // projection temp / attn out
__device__ float g_q[(size_t)BSZ * CH * TT];   // [B,H,T,D]
__device__ float g_k[(size_t)BSZ * CH * TT];
__device__ float g_v[(size_t)BSZ * CH * TT];

// ---------------------------------------------------------------------------
// SGEMM: Out[b][m][n] = sum_k W[m][k] * X[b][k][n] + bias[m]
// W: [C,C]; X: [B,C,T]; Out: [B,C,T]
// grid (T/64, C/64, B), block (16,16); 64x64 tile, BK=16, 4x4 per thread.
// ---------------------------------------------------------------------------
__global__ void __launch_bounds__(256) sgemm_bias(
    const float* __restrict__ W, const float* __restrict__ X,
    const float* __restrict__ bias, float* __restrict__ Out) {
  __shared__ float Ws[16][64];
  __shared__ float Xs[16][64];
  const float* Xb = X + (size_t)blockIdx.z * CH * TT;
  float* Ob = Out + (size_t)blockIdx.z * CH * TT;
  const int m0 = blockIdx.y * 64, n0 = blockIdx.x * 64;
  const int tx = threadIdx.x, ty = threadIdx.y;
  const int tid = ty * 16 + tx;

  // load-index precompute
  const int mw = tid >> 2;          // 0..63 (W row within tile)
  const int kw = (tid & 3) * 4;     // 0..12 (W k within tile)
  const int kx = tid >> 4;          // 0..15 (X k within tile)
  const int nx = (tid & 15) * 4;    // 0..60 (X n within tile)

  float acc[4][4] = {};

  for (int k0 = 0; k0 < CH; k0 += 16) {
    float4 w4 = *(const float4*)&W[(size_t)(m0 + mw) * CH + k0 + kw];
    Ws[kw + 0][mw] = w4.x; Ws[kw + 1][mw] = w4.y;
    Ws[kw + 2][mw] = w4.z; Ws[kw + 3][mw] = w4.w;
    *(float4*)&Xs[kx][nx] =
        *(const float4*)&Xb[(size_t)(k0 + kx) * TT + n0 + nx];
    __syncthreads();
#pragma unroll
    for (int kk = 0; kk < 16; kk++) {
      float4 a4 = *(const float4*)&Ws[kk][ty * 4];
      float4 b4 = *(const float4*)&Xs[kk][tx * 4];
      float a[4] = {a4.x, a4.y, a4.z, a4.w};
      float b[4] = {b4.x, b4.y, b4.z, b4.w};
#pragma unroll
      for (int i = 0; i < 4; i++)
#pragma unroll
        for (int j = 0; j < 4; j++) acc[i][j] += a[i] * b[j];
    }
    __syncthreads();
  }

#pragma unroll
  for (int i = 0; i < 4; i++) {
    int mm = m0 + ty * 4 + i;
    float bv = bias[mm];
    float4 r = make_float4(acc[i][0] + bv, acc[i][1] + bv,
                           acc[i][2] + bv, acc[i][3] + bv);
    *(float4*)&Ob[(size_t)mm * TT + n0 + tx * 4] = r;
  }
}

// ---------------------------------------------------------------------------
// Transpose [B*H, D=64, T] -> [B*H, T, D], optionally applying RoPE.
// grid (T/64, B*H), block 256. smem tile 64x65 (pad kills bank conflicts).
// ---------------------------------------------------------------------------
__global__ void __launch_bounds__(256) rope_transpose(
    const float* __restrict__ P, float* __restrict__ Out, int applyRope) {
  __shared__ float tile[64][65];
  const int bh = blockIdx.y;
  const int t0 = blockIdx.x * 64;
  const int tid = threadIdx.x;

  // load: t fastest (coalesced on P)
  const int tl = tid & 63;
#pragma unroll
  for (int d = tid >> 6; d < 64; d += 4)
    tile[d][tl] = P[((size_t)bh * 64 + d) * TT + t0 + tl];
  __syncthreads();

  // write: d fastest (coalesced on Out)
  const int d = tid & 63;
#pragma unroll
  for (int ttt = tid >> 6; ttt < 64; ttt += 4) {
    int t = t0 + ttt;
    float val = tile[d][ttt];
    if (applyRope && d < RD) {
      int j = (d < RH) ? d : (d - RH);
      float theta = powf(10000.0f, -(float)(2 * j) / (float)RD);
      float ang = (float)t * theta;
      float c = cosf(ang), s = sinf(ang);
      if (d < RH)
        val = tile[d][ttt] * c - tile[d + RH][ttt] * s;
      else
        val = tile[d][ttt] * c + tile[d - RH][ttt] * s;
    }
    Out[((size_t)bh * TT + t) * 64 + d] = val;
  }
}

// ---------------------------------------------------------------------------
// Flash-style attention.
// Q,K,V: [B,H,T,D]; AO written as [B, h*64+d, T] (projection-input layout).
// grid (T/128, H, B), block 128. One thread = one query row.
// ---------------------------------------------------------------------------
#define KT 16
__global__ void __launch_bounds__(128) attn_kernel(
    const float* __restrict__ Q, const float* __restrict__ K,
    const float* __restrict__ V, const int* __restrict__ mask,
    float* __restrict__ AO) {
  const int b = blockIdx.z, h = blockIdx.y;
  const int t = blockIdx.x * 128 + threadIdx.x;
  const size_t bh = (size_t)b * NH + h;

  __shared__ float Ks[KT][64];
  __shared__ float Vs[KT][64];

  const float* qrow = Q + (bh * TT + t) * 64;
  float q[64];
#pragma unroll
  for (int i = 0; i < 16; i++) {
    float4 v4 = ((const float4*)qrow)[i];
    q[4 * i + 0] = v4.x; q[4 * i + 1] = v4.y;
    q[4 * i + 2] = v4.z; q[4 * i + 3] = v4.w;
  }

  float acc[64];
#pragma unroll
  for (int i = 0; i < 64; i++) acc[i] = 0.0f;
  float m = -INFINITY, l = 0.0f;

  const float* Kb = K + bh * TT * 64;
  const float* Vb = V + bh * TT * 64;
  const int* mb = mask + (size_t)b * TT;
  const float tf = (float)t;

  for (int k0 = 0; k0 < TT; k0 += KT) {
    __syncthreads();
#pragma unroll
    for (int i = threadIdx.x; i < KT * 64 / 4; i += 128) {
      ((float4*)&Ks[0][0])[i] = ((const float4*)(Kb + (size_t)k0 * 64))[i];
      ((float4*)&Vs[0][0])[i] = ((const float4*)(Vb + (size_t)k0 * 64))[i];
    }
    __syncthreads();

    float s[KT];
    float tmax = -INFINITY;
#pragma unroll
    for (int j = 0; j < KT; j++) {
      float d0 = 0.0f;
#pragma unroll
      for (int dd = 0; dd < 64; dd++) d0 += q[dd] * Ks[j][dd];
      int kp = k0 + j;
      float sc = d0 * 0.125f - log1pf(fabsf(tf - (float)kp));
      if (mb[kp] == 0) sc = -10000.0f;
      s[j] = sc;
      tmax = fmaxf(tmax, sc);
    }

    float mnew = fmaxf(m, tmax);
    float scale = expf(m - mnew);   // first iter: exp(-inf)=0
    l *= scale;
#pragma unroll
    for (int dd = 0; dd < 64; dd++) acc[dd] *= scale;
#pragma unroll
    for (int j = 0; j < KT; j++) {
      float p = expf(s[j] - mnew);
      l += p;
#pragma unroll
      for (int dd = 0; dd < 64; dd++) acc[dd] += p * Vs[j][dd];
    }
    m = mnew;
  }

  float inv = 1.0f / l;
  float* ao = AO + ((size_t)b * CH + (size_t)h * 64) * TT + t;
#pragma unroll
  for (int d = 0; d < 64; d++) ao[(size_t)d * TT] = acc[d] * inv;
}

// ---------------------------------------------------------------------------
extern "C" void kernel_launch(void* const* d_in, const int* in_sizes, int n_in,
                              void* d_out, int out_size) {
  const float* x    = (const float*)d_in[0];
  const float* ctx  = (const float*)d_in[1];
  const int*   mask = (const int*)d_in[2];
  const float* Wq   = (const float*)d_in[3];
  const float* bq   = (const float*)d_in[4];
  const float* Wk   = (const float*)d_in[5];
  const float* bk   = (const float*)d_in[6];
  const float* Wv   = (const float*)d_in[7];
  const float* bv   = (const float*)d_in[8];
  const float* Wo   = (const float*)d_in[9];
  const float* bo   = (const float*)d_in[10];
  float* out = (float*)d_out;

  float *p, *q, *k, *v;
  cudaGetSymbolAddress((void**)&p, g_p);
  cudaGetSymbolAddress((void**)&q, g_q);
  cudaGetSymbolAddress((void**)&k, g_k);
  cudaGetSymbolAddress((void**)&v, g_v);

  dim3 gg(TT / 64, CH / 64, BSZ), gb(16, 16);
  dim3 tg(TT / 64, BSZ * NH);
  dim3 ag(TT / 128, NH, BSZ);

  // Q projection + rope
  sgemm_bias<<<gg, gb>>>(Wq, x, bq, p);
  rope_transpose<<<tg, 256>>>(p, q, 1);
  // K projection + rope
  sgemm_bias<<<gg, gb>>>(Wk, ctx, bk, p);
  rope_transpose<<<tg, 256>>>(p, k, 1);
  // V projection
  sgemm_bias<<<gg, gb>>>(Wv, ctx, bv, p);
  rope_transpose<<<tg, 256>>>(p, v, 0);
  // attention -> p in [B, C, T] layout
  attn_kernel<<<ag, 128>>>(q, k, v, mask, p);
  // output projection
  sgemm_bias<<<gg, gb>>>(Wo, p, bo, out);
}

// round 3
// speedup vs baseline: 1.5450x; 1.5450x over previous
#include <cuda_runtime.h>
#include <math.h>

#define BSZ 8
#define CH  1024
#define TT  1024
#define NH  16
#define HD  64
#define RD  32   // rope dim
#define RH  16   // rope half

// ---------------- scratch (device globals; no allocation allowed) ----------
__device__ float g_p[(size_t)BSZ * CH * TT];   // projection temp / attn out
__device__ float g_q[(size_t)BSZ * CH * TT];   // [B,H,T,D]
__device__ float g_k[(size_t)BSZ * CH * TT];
__device__ float g_v[(size_t)BSZ * CH * TT];

// ---------------------------------------------------------------------------
__device__ __forceinline__ unsigned f2tf32(float x) {
  unsigned r;
  asm("cvt.rna.tf32.f32 %0, %1;" : "=r"(r) : "f"(x));
  return r;
}

__device__ __forceinline__ void mma_tf32(float c[4], unsigned a0, unsigned a1,
                                         unsigned a2, unsigned a3, unsigned b0,
                                         unsigned b1) {
  asm volatile(
      "mma.sync.aligned.m16n8k8.row.col.f32.tf32.tf32.f32 "
      "{%0,%1,%2,%3}, {%4,%5,%6,%7}, {%8,%9}, {%0,%1,%2,%3};"
      : "+f"(c[0]), "+f"(c[1]), "+f"(c[2]), "+f"(c[3])
      : "r"(a0), "r"(a1), "r"(a2), "r"(a3), "r"(b0), "r"(b1));
}

// ---------------------------------------------------------------------------
// TF32 tensor-core GEMM: Out[b][m][n] = sum_k W[m][k]*X[b][k][n] + bias[m]
// W:[C,C] row-major (m,k); X:[B,C,T] (k,n); Out:[B,C,T].
// grid (T/128, C/128, B), 256 threads (8 warps, 2m x 4n), warp tile 64x32.
// ---------------------------------------------------------------------------
__global__ void __launch_bounds__(256) gemm_tf32(
    const float* __restrict__ W, const float* __restrict__ X,
    const float* __restrict__ bias, float* __restrict__ Out) {
  // A smem: [m][k], stride 36 -> fragment loads conflict-free (4r+c banks)
  __shared__ unsigned As[128][36];
  // B smem: [k][n], stride 136 -> fragment loads conflict-free (8k+n banks)
  __shared__ unsigned Bs[32][136];

  const float* Xb = X + (size_t)blockIdx.z * CH * TT;
  float* Ob = Out + (size_t)blockIdx.z * CH * TT;
  const int m0 = blockIdx.y * 128, n0 = blockIdx.x * 128;
  const int tid = threadIdx.x;
  const int warp = tid >> 5, lane = tid & 31;
  const int wm = warp & 1, wn = warp >> 1;    // warp tile: rows wm*64, cols wn*32
  const int g = lane >> 2, tg = lane & 3;     // mma lane decomposition

  // global->smem index precompute
  const int am = tid >> 3;          // 0..31 (row within 32-row pass)
  const int ak = (tid & 7) * 4;     // 0..28
  const int bk = tid >> 5;          // 0..7  (k within 8-row pass)
  const int bn = (tid & 31) * 4;    // 0..124

  float acc[4][4][4];
#pragma unroll
  for (int i = 0; i < 4; i++)
#pragma unroll
    for (int j = 0; j < 4; j++)
#pragma unroll
      for (int r = 0; r < 4; r++) acc[i][j][r] = 0.0f;

  for (int k0 = 0; k0 < CH; k0 += 32) {
    // load A tile 128x32 (coalesced along k), cvt->tf32, store [m][k]
#pragma unroll
    for (int p = 0; p < 4; p++) {
      int m = p * 32 + am;
      float4 w4 = *(const float4*)&W[(size_t)(m0 + m) * CH + k0 + ak];
      As[m][ak + 0] = f2tf32(w4.x);
      As[m][ak + 1] = f2tf32(w4.y);
      As[m][ak + 2] = f2tf32(w4.z);
      As[m][ak + 3] = f2tf32(w4.w);
    }
    // load B tile 32x128 (coalesced along n), cvt->tf32, store [k][n]
#pragma unroll
    for (int p = 0; p < 4; p++) {
      int k = p * 8 + bk;
      float4 x4 = *(const float4*)&Xb[(size_t)(k0 + k) * TT + n0 + bn];
      uint4 u;
      u.x = f2tf32(x4.x); u.y = f2tf32(x4.y);
      u.z = f2tf32(x4.z); u.w = f2tf32(x4.w);
      *(uint4*)&Bs[k][bn] = u;
    }
    __syncthreads();

#pragma unroll
    for (int ks = 0; ks < 4; ks++) {
      const int kk = ks * 8;
      unsigned a[4][4], b[4][2];
#pragma unroll
      for (int mi = 0; mi < 4; mi++) {
        int row = wm * 64 + mi * 16 + g;
        a[mi][0] = As[row][kk + tg];
        a[mi][1] = As[row + 8][kk + tg];
        a[mi][2] = As[row][kk + tg + 4];
        a[mi][3] = As[row + 8][kk + tg + 4];
      }
#pragma unroll
      for (int ni = 0; ni < 4; ni++) {
        int col = wn * 32 + ni * 8 + g;
        b[ni][0] = Bs[kk + tg][col];
        b[ni][1] = Bs[kk + tg + 4][col];
      }
#pragma unroll
      for (int mi = 0; mi < 4; mi++)
#pragma unroll
        for (int ni = 0; ni < 4; ni++)
          mma_tf32(acc[mi][ni], a[mi][0], a[mi][1], a[mi][2], a[mi][3],
                   b[ni][0], b[ni][1]);
    }
    __syncthreads();
  }

  // epilogue: c0/c1 -> (row, 2tg..2tg+1), c2/c3 -> (row+8, ...)
#pragma unroll
  for (int mi = 0; mi < 4; mi++) {
    int row = m0 + wm * 64 + mi * 16 + g;
    float bv0 = bias[row];
    float bv1 = bias[row + 8];
#pragma unroll
    for (int ni = 0; ni < 4; ni++) {
      int col = n0 + wn * 32 + ni * 8 + 2 * tg;
      float2 r0 = make_float2(acc[mi][ni][0] + bv0, acc[mi][ni][1] + bv0);
      float2 r1 = make_float2(acc[mi][ni][2] + bv1, acc[mi][ni][3] + bv1);
      *(float2*)&Ob[(size_t)row * TT + col] = r0;
      *(float2*)&Ob[(size_t)(row + 8) * TT + col] = r1;
    }
  }
}

// ---------------------------------------------------------------------------
// Transpose [B*H, D=64, T] -> [B*H, T, D], optionally applying RoPE.
// ---------------------------------------------------------------------------
__global__ void __launch_bounds__(256) rope_transpose(
    const float* __restrict__ P, float* __restrict__ Out, int applyRope) {
  __shared__ float tile[64][65];
  const int bh = blockIdx.y;
  const int t0 = blockIdx.x * 64;
  const int tid = threadIdx.x;

  const int tl = tid & 63;
#pragma unroll
  for (int d = tid >> 6; d < 64; d += 4)
    tile[d][tl] = P[((size_t)bh * 64 + d) * TT + t0 + tl];
  __syncthreads();

  const int d = tid & 63;
#pragma unroll
  for (int ttt = tid >> 6; ttt < 64; ttt += 4) {
    int t = t0 + ttt;
    float val = tile[d][ttt];
    if (applyRope && d < RD) {
      int j = (d < RH) ? d : (d - RH);
      float theta = powf(10000.0f, -(float)(2 * j) / (float)RD);
      float ang = (float)t * theta;
      float c = cosf(ang), s = sinf(ang);
      if (d < RH)
        val = tile[d][ttt] * c - tile[d + RH][ttt] * s;
      else
        val = tile[d][ttt] * c + tile[d - RH][ttt] * s;
    }
    Out[((size_t)bh * TT + t) * 64 + d] = val;
  }
}

// ---------------------------------------------------------------------------
// Flash-style attention (unchanged from R1).
// ---------------------------------------------------------------------------
#define KT 16
__global__ void __launch_bounds__(128) attn_kernel(
    const float* __restrict__ Q, const float* __restrict__ K,
    const float* __restrict__ V, const int* __restrict__ mask,
    float* __restrict__ AO) {
  const int b = blockIdx.z, h = blockIdx.y;
  const int t = blockIdx.x * 128 + threadIdx.x;
  const size_t bh = (size_t)b * NH + h;

  __shared__ float Ks[KT][64];
  __shared__ float Vs[KT][64];

  const float* qrow = Q + (bh * TT + t) * 64;
  float q[64];
#pragma unroll
  for (int i = 0; i < 16; i++) {
    float4 v4 = ((const float4*)qrow)[i];
    q[4 * i + 0] = v4.x; q[4 * i + 1] = v4.y;
    q[4 * i + 2] = v4.z; q[4 * i + 3] = v4.w;
  }

  float acc[64];
#pragma unroll
  for (int i = 0; i < 64; i++) acc[i] = 0.0f;
  float m = -INFINITY, l = 0.0f;

  const float* Kb = K + bh * TT * 64;
  const float* Vb = V + bh * TT * 64;
  const int* mb = mask + (size_t)b * TT;
  const float tf = (float)t;

  for (int k0 = 0; k0 < TT; k0 += KT) {
    __syncthreads();
#pragma unroll
    for (int i = threadIdx.x; i < KT * 64 / 4; i += 128) {
      ((float4*)&Ks[0][0])[i] = ((const float4*)(Kb + (size_t)k0 * 64))[i];
      ((float4*)&Vs[0][0])[i] = ((const float4*)(Vb + (size_t)k0 * 64))[i];
    }
    __syncthreads();

    float s[KT];
    float tmax = -INFINITY;
#pragma unroll
    for (int j = 0; j < KT; j++) {
      float d0 = 0.0f;
#pragma unroll
      for (int dd = 0; dd < 64; dd++) d0 += q[dd] * Ks[j][dd];
      int kp = k0 + j;
      float sc = d0 * 0.125f - log1pf(fabsf(tf - (float)kp));
      if (mb[kp] == 0) sc = -10000.0f;
      s[j] = sc;
      tmax = fmaxf(tmax, sc);
    }

    float mnew = fmaxf(m, tmax);
    float scale = expf(m - mnew);
    l *= scale;
#pragma unroll
    for (int dd = 0; dd < 64; dd++) acc[dd] *= scale;
#pragma unroll
    for (int j = 0; j < KT; j++) {
      float p = expf(s[j] - mnew);
      l += p;
#pragma unroll
      for (int dd = 0; dd < 64; dd++) acc[dd] += p * Vs[j][dd];
    }
    m = mnew;
  }

  float inv = 1.0f / l;
  float* ao = AO + ((size_t)b * CH + (size_t)h * 64) * TT + t;
#pragma unroll
  for (int d = 0; d < 64; d++) ao[(size_t)d * TT] = acc[d] * inv;
}

// ---------------------------------------------------------------------------
extern "C" void kernel_launch(void* const* d_in, const int* in_sizes, int n_in,
                              void* d_out, int out_size) {
  const float* x    = (const float*)d_in[0];
  const float* ctx  = (const float*)d_in[1];
  const int*   mask = (const int*)d_in[2];
  const float* Wq   = (const float*)d_in[3];
  const float* bq   = (const float*)d_in[4];
  const float* Wk   = (const float*)d_in[5];
  const float* bk   = (const float*)d_in[6];
  const float* Wv   = (const float*)d_in[7];
  const float* bv   = (const float*)d_in[8];
  const float* Wo   = (const float*)d_in[9];
  const float* bo   = (const float*)d_in[10];
  float* out = (float*)d_out;

  float *p, *q, *k, *v;
  cudaGetSymbolAddress((void**)&p, g_p);
  cudaGetSymbolAddress((void**)&q, g_q);
  cudaGetSymbolAddress((void**)&k, g_k);
  cudaGetSymbolAddress((void**)&v, g_v);

  dim3 gg(TT / 128, CH / 128, BSZ);
  dim3 tg(TT / 64, BSZ * NH);
  dim3 ag(TT / 128, NH, BSZ);

  gemm_tf32<<<gg, 256>>>(Wq, x, bq, p);
  rope_transpose<<<tg, 256>>>(p, q, 1);
  gemm_tf32<<<gg, 256>>>(Wk, ctx, bk, p);
  rope_transpose<<<tg, 256>>>(p, k, 1);
  gemm_tf32<<<gg, 256>>>(Wv, ctx, bv, p);
  rope_transpose<<<tg, 256>>>(p, v, 0);
  attn_kernel<<<ag, 128>>>(q, k, v, mask, p);
  gemm_tf32<<<gg, 256>>>(Wo, p, bo, out);
}

// round 4
// speedup vs baseline: 4.1327x; 2.6749x over previous
#include <cuda_runtime.h>
#include <math.h>

#define BSZ 8
#define CH  1024
#define TT  1024
#define NH  16
#define HD  64
#define RD  32   // rope dim
#define RH  16   // rope half

// ---------------- scratch (device globals; no allocation allowed) ----------
__device__ float g_p[(size_t)BSZ * CH * TT];   // projection temp / attn out
__device__ float g_q[(size_t)BSZ * CH * TT];   // [B,H,T,D]
__device__ float g_k[(size_t)BSZ * CH * TT];
__device__ float g_v[(size_t)BSZ * CH * TT];

// ---------------------------------------------------------------------------
__device__ __forceinline__ unsigned f2tf32(float x) {
  unsigned r;
  asm("cvt.rna.tf32.f32 %0, %1;" : "=r"(r) : "f"(x));
  return r;
}

__device__ __forceinline__ void mma_tf32(float c[4], unsigned a0, unsigned a1,
                                         unsigned a2, unsigned a3, unsigned b0,
                                         unsigned b1) {
  asm volatile(
      "mma.sync.aligned.m16n8k8.row.col.f32.tf32.tf32.f32 "
      "{%0,%1,%2,%3}, {%4,%5,%6,%7}, {%8,%9}, {%0,%1,%2,%3};"
      : "+f"(c[0]), "+f"(c[1]), "+f"(c[2]), "+f"(c[3])
      : "r"(a0), "r"(a1), "r"(a2), "r"(a3), "r"(b0), "r"(b1));
}

// ---------------------------------------------------------------------------
// TF32 tensor-core GEMM: Out[b][m][n] = sum_k W[m][k]*X[b][k][n] + bias[m]
// ---------------------------------------------------------------------------
__global__ void __launch_bounds__(256) gemm_tf32(
    const float* __restrict__ W, const float* __restrict__ X,
    const float* __restrict__ bias, float* __restrict__ Out) {
  __shared__ unsigned As[128][36];
  __shared__ unsigned Bs[32][136];

  const float* Xb = X + (size_t)blockIdx.z * CH * TT;
  float* Ob = Out + (size_t)blockIdx.z * CH * TT;
  const int m0 = blockIdx.y * 128, n0 = blockIdx.x * 128;
  const int tid = threadIdx.x;
  const int warp = tid >> 5, lane = tid & 31;
  const int wm = warp & 1, wn = warp >> 1;
  const int g = lane >> 2, tg = lane & 3;

  const int am = tid >> 3;
  const int ak = (tid & 7) * 4;
  const int bk = tid >> 5;
  const int bn = (tid & 31) * 4;

  float acc[4][4][4];
#pragma unroll
  for (int i = 0; i < 4; i++)
#pragma unroll
    for (int j = 0; j < 4; j++)
#pragma unroll
      for (int r = 0; r < 4; r++) acc[i][j][r] = 0.0f;

  for (int k0 = 0; k0 < CH; k0 += 32) {
#pragma unroll
    for (int p = 0; p < 4; p++) {
      int m = p * 32 + am;
      float4 w4 = *(const float4*)&W[(size_t)(m0 + m) * CH + k0 + ak];
      As[m][ak + 0] = f2tf32(w4.x);
      As[m][ak + 1] = f2tf32(w4.y);
      As[m][ak + 2] = f2tf32(w4.z);
      As[m][ak + 3] = f2tf32(w4.w);
    }
#pragma unroll
    for (int p = 0; p < 4; p++) {
      int k = p * 8 + bk;
      float4 x4 = *(const float4*)&Xb[(size_t)(k0 + k) * TT + n0 + bn];
      uint4 u;
      u.x = f2tf32(x4.x); u.y = f2tf32(x4.y);
      u.z = f2tf32(x4.z); u.w = f2tf32(x4.w);
      *(uint4*)&Bs[k][bn] = u;
    }
    __syncthreads();

#pragma unroll
    for (int ks = 0; ks < 4; ks++) {
      const int kk = ks * 8;
      unsigned a[4][4], b[4][2];
#pragma unroll
      for (int mi = 0; mi < 4; mi++) {
        int row = wm * 64 + mi * 16 + g;
        a[mi][0] = As[row][kk + tg];
        a[mi][1] = As[row + 8][kk + tg];
        a[mi][2] = As[row][kk + tg + 4];
        a[mi][3] = As[row + 8][kk + tg + 4];
      }
#pragma unroll
      for (int ni = 0; ni < 4; ni++) {
        int col = wn * 32 + ni * 8 + g;
        b[ni][0] = Bs[kk + tg][col];
        b[ni][1] = Bs[kk + tg + 4][col];
      }
#pragma unroll
      for (int mi = 0; mi < 4; mi++)
#pragma unroll
        for (int ni = 0; ni < 4; ni++)
          mma_tf32(acc[mi][ni], a[mi][0], a[mi][1], a[mi][2], a[mi][3],
                   b[ni][0], b[ni][1]);
    }
    __syncthreads();
  }

#pragma unroll
  for (int mi = 0; mi < 4; mi++) {
    int row = m0 + wm * 64 + mi * 16 + g;
    float bv0 = bias[row];
    float bv1 = bias[row + 8];
#pragma unroll
    for (int ni = 0; ni < 4; ni++) {
      int col = n0 + wn * 32 + ni * 8 + 2 * tg;
      float2 r0 = make_float2(acc[mi][ni][0] + bv0, acc[mi][ni][1] + bv0);
      float2 r1 = make_float2(acc[mi][ni][2] + bv1, acc[mi][ni][3] + bv1);
      *(float2*)&Ob[(size_t)row * TT + col] = r0;
      *(float2*)&Ob[(size_t)(row + 8) * TT + col] = r1;
    }
  }
}

// ---------------------------------------------------------------------------
// Transpose [B*H, D=64, T] -> [B*H, T, D], optionally applying RoPE.
// ---------------------------------------------------------------------------
__global__ void __launch_bounds__(256) rope_transpose(
    const float* __restrict__ P, float* __restrict__ Out, int applyRope) {
  __shared__ float tile[64][65];
  const int bh = blockIdx.y;
  const int t0 = blockIdx.x * 64;
  const int tid = threadIdx.x;

  const int tl = tid & 63;
#pragma unroll
  for (int d = tid >> 6; d < 64; d += 4)
    tile[d][tl] = P[((size_t)bh * 64 + d) * TT + t0 + tl];
  __syncthreads();

  const int d = tid & 63;
#pragma unroll
  for (int ttt = tid >> 6; ttt < 64; ttt += 4) {
    int t = t0 + ttt;
    float val = tile[d][ttt];
    if (applyRope && d < RD) {
      int j = (d < RH) ? d : (d - RH);
      float theta = powf(10000.0f, -(float)(2 * j) / (float)RD);
      float ang = (float)t * theta;
      float c = cosf(ang), s = sinf(ang);
      if (d < RH)
        val = tile[d][ttt] * c - tile[d + RH][ttt] * s;
      else
        val = tile[d][ttt] * c + tile[d - RH][ttt] * s;
    }
    Out[((size_t)bh * TT + t) * 64 + d] = val;
  }
}

// ---------------------------------------------------------------------------
// Tensor-core flash attention (tf32 mma, 64 q-rows/CTA, 64-key tiles).
// Q,K,V: [B,H,T,D] fp32. AO: [B, h*64+d, T].
// grid (T/64, H, B), 128 threads (4 warps, warp = 16 q-rows).
// ---------------------------------------------------------------------------
#define ASTR 68           // smem stride (words) for 64-wide tf32 tiles
#define ATT_SMEM (3 * 64 * ASTR * 4 + 1024 * 4 + 64 * 4)

__global__ void __launch_bounds__(128) attn_mma(
    const float* __restrict__ Q, const float* __restrict__ K,
    const float* __restrict__ V, const int* __restrict__ mask,
    float* __restrict__ AO) {
  extern __shared__ char smraw[];
  unsigned* Ks = (unsigned*)smraw;            // [64][ASTR]  (keys x d)
  unsigned* Vs = Ks + 64 * ASTR;              // [64][ASTR]  (keys x d)
  unsigned* Ps = Vs + 64 * ASTR;              // [64][ASTR]  (qrow x key); Q staging
  float* bias_t = (float*)(Ps + 64 * ASTR);   // [1024]
  int* msk = (int*)(bias_t + 1024);           // [64]
  float* Od = (float*)Ks;                     // reuse for output staging [64][ASTR]

  const int tid = threadIdx.x;
  const int warp = tid >> 5, lane = tid & 31;
  const int g = lane >> 2, tg = lane & 3;
  const int b = blockIdx.z, h = blockIdx.y, q0 = blockIdx.x * 64;
  const size_t bh = (size_t)b * NH + h;
  const float* Qb = Q + (bh * TT + q0) * 64;
  const float* Kb = K + bh * TT * 64;
  const float* Vb = V + bh * TT * 64;
  const int* mb = mask + (size_t)b * TT;

  for (int i = tid; i < 1024; i += 128) bias_t[i] = -log1pf((float)i);

  // stage Q tile (pre-scaled by 1/8, tf32) into Ps
#pragma unroll
  for (int i = 0; i < 8; i++) {
    int idx = i * 128 + tid;
    int row = idx >> 4, c4 = (idx & 15) * 4;
    float4 v4 = *(const float4*)&Qb[row * 64 + c4];
    uint4 u;
    u.x = f2tf32(v4.x * 0.125f); u.y = f2tf32(v4.y * 0.125f);
    u.z = f2tf32(v4.z * 0.125f); u.w = f2tf32(v4.w * 0.125f);
    *(uint4*)&Ps[row * ASTR + c4] = u;
  }
  __syncthreads();

  const int r0 = warp * 16 + g;     // local q-row for c0/c1 (c2/c3: +8)
  unsigned aq[8][4];
#pragma unroll
  for (int kc = 0; kc < 8; kc++) {
    aq[kc][0] = Ps[r0 * ASTR + kc * 8 + tg];
    aq[kc][1] = Ps[(r0 + 8) * ASTR + kc * 8 + tg];
    aq[kc][2] = Ps[r0 * ASTR + kc * 8 + tg + 4];
    aq[kc][3] = Ps[(r0 + 8) * ASTR + kc * 8 + tg + 4];
  }

  float accO[8][4];
#pragma unroll
  for (int nt = 0; nt < 8; nt++)
#pragma unroll
    for (int i = 0; i < 4; i++) accO[nt][i] = 0.0f;
  float m0r = -INFINITY, m1r = -INFINITY, l0r = 0.0f, l1r = 0.0f;
  const int trow0 = q0 + r0, trow1 = trow0 + 8;

  for (int k0 = 0; k0 < TT; k0 += 64) {
    __syncthreads();   // protect prev iter's Ks/Vs/Ps reads
#pragma unroll
    for (int i = 0; i < 8; i++) {
      int idx = i * 128 + tid;
      int row = idx >> 4, c4 = (idx & 15) * 4;
      float4 kv = *(const float4*)&Kb[(size_t)(k0 + row) * 64 + c4];
      uint4 uk;
      uk.x = f2tf32(kv.x); uk.y = f2tf32(kv.y);
      uk.z = f2tf32(kv.z); uk.w = f2tf32(kv.w);
      *(uint4*)&Ks[row * ASTR + c4] = uk;
      float4 vv = *(const float4*)&Vb[(size_t)(k0 + row) * 64 + c4];
      uint4 uv;
      uv.x = f2tf32(vv.x); uv.y = f2tf32(vv.y);
      uv.z = f2tf32(vv.z); uv.w = f2tf32(vv.w);
      *(uint4*)&Vs[row * ASTR + c4] = uv;
    }
    if (tid < 64) msk[tid] = mb[k0 + tid];
    __syncthreads();

    // S = Q * K^T (per warp: 16 x 64)
    float s[8][4];
#pragma unroll
    for (int nt = 0; nt < 8; nt++) {
      float c[4] = {0.0f, 0.0f, 0.0f, 0.0f};
#pragma unroll
      for (int kc = 0; kc < 8; kc++) {
        unsigned b0 = Ks[(nt * 8 + g) * ASTR + kc * 8 + tg];
        unsigned b1 = Ks[(nt * 8 + g) * ASTR + kc * 8 + tg + 4];
        mma_tf32(c, aq[kc][0], aq[kc][1], aq[kc][2], aq[kc][3], b0, b1);
      }
      int kl = nt * 8 + 2 * tg;      // local key for c0/c2 (c1/c3: +1)
      int kA = k0 + kl;
      s[nt][0] = (msk[kl] == 0) ? -10000.0f : c[0] + bias_t[abs(trow0 - kA)];
      s[nt][1] = (msk[kl + 1] == 0) ? -10000.0f : c[1] + bias_t[abs(trow0 - kA - 1)];
      s[nt][2] = (msk[kl] == 0) ? -10000.0f : c[2] + bias_t[abs(trow1 - kA)];
      s[nt][3] = (msk[kl + 1] == 0) ? -10000.0f : c[3] + bias_t[abs(trow1 - kA - 1)];
    }

    // row maxima (regs + quad shfl)
    float tm0 = -INFINITY, tm1 = -INFINITY;
#pragma unroll
    for (int nt = 0; nt < 8; nt++) {
      tm0 = fmaxf(tm0, fmaxf(s[nt][0], s[nt][1]));
      tm1 = fmaxf(tm1, fmaxf(s[nt][2], s[nt][3]));
    }
    tm0 = fmaxf(tm0, __shfl_xor_sync(0xffffffffu, tm0, 1));
    tm0 = fmaxf(tm0, __shfl_xor_sync(0xffffffffu, tm0, 2));
    tm1 = fmaxf(tm1, __shfl_xor_sync(0xffffffffu, tm1, 1));
    tm1 = fmaxf(tm1, __shfl_xor_sync(0xffffffffu, tm1, 2));
    float mn0 = fmaxf(m0r, tm0), mn1 = fmaxf(m1r, tm1);
    float sc0 = __expf(m0r - mn0), sc1 = __expf(m1r - mn1);
    m0r = mn0; m1r = mn1;

    // P = exp(s - m), store tf32 to per-warp Ps region
    float ps0 = 0.0f, ps1 = 0.0f;
#pragma unroll
    for (int nt = 0; nt < 8; nt++) {
      int col = nt * 8 + 2 * tg;
      float p0 = __expf(s[nt][0] - mn0);
      float p1 = __expf(s[nt][1] - mn0);
      float p2 = __expf(s[nt][2] - mn1);
      float p3 = __expf(s[nt][3] - mn1);
      ps0 += p0 + p1; ps1 += p2 + p3;
      Ps[r0 * ASTR + col] = f2tf32(p0);
      Ps[r0 * ASTR + col + 1] = f2tf32(p1);
      Ps[(r0 + 8) * ASTR + col] = f2tf32(p2);
      Ps[(r0 + 8) * ASTR + col + 1] = f2tf32(p3);
    }
    ps0 += __shfl_xor_sync(0xffffffffu, ps0, 1);
    ps0 += __shfl_xor_sync(0xffffffffu, ps0, 2);
    ps1 += __shfl_xor_sync(0xffffffffu, ps1, 1);
    ps1 += __shfl_xor_sync(0xffffffffu, ps1, 2);
    l0r = l0r * sc0 + ps0;
    l1r = l1r * sc1 + ps1;

#pragma unroll
    for (int nt = 0; nt < 8; nt++) {
      accO[nt][0] *= sc0; accO[nt][1] *= sc0;
      accO[nt][2] *= sc1; accO[nt][3] *= sc1;
    }

    __syncwarp();  // order P stores before cross-lane A-fragment reads

    // O += P * V
#pragma unroll
    for (int kc = 0; kc < 8; kc++) {
      unsigned a0 = Ps[r0 * ASTR + kc * 8 + tg];
      unsigned a1 = Ps[(r0 + 8) * ASTR + kc * 8 + tg];
      unsigned a2 = Ps[r0 * ASTR + kc * 8 + tg + 4];
      unsigned a3 = Ps[(r0 + 8) * ASTR + kc * 8 + tg + 4];
#pragma unroll
      for (int nt = 0; nt < 8; nt++) {
        unsigned b0 = Vs[(kc * 8 + tg) * ASTR + nt * 8 + g];
        unsigned b1 = Vs[(kc * 8 + tg + 4) * ASTR + nt * 8 + g];
        mma_tf32(accO[nt], a0, a1, a2, a3, b0, b1);
      }
    }
  }

  // stage output (d-major) and write coalesced along t
  __syncthreads();
  float inv0 = 1.0f / l0r, inv1 = 1.0f / l1r;
#pragma unroll
  for (int nt = 0; nt < 8; nt++) {
    int d = nt * 8 + 2 * tg;
    Od[d * ASTR + r0] = accO[nt][0] * inv0;
    Od[(d + 1) * ASTR + r0] = accO[nt][1] * inv0;
    Od[d * ASTR + r0 + 8] = accO[nt][2] * inv1;
    Od[(d + 1) * ASTR + r0 + 8] = accO[nt][3] * inv1;
  }
  __syncthreads();
  {
    int d = tid >> 1;
    int c0 = (tid & 1) * 32;
    float* ao = AO + ((size_t)b * CH + (size_t)h * 64 + d) * TT + q0 + c0;
#pragma unroll
    for (int i = 0; i < 8; i++) {
      float4 o4 = *(float4*)&Od[d * ASTR + c0 + i * 4];
      *(float4*)&ao[i * 4] = o4;
    }
  }
}

// ---------------------------------------------------------------------------
extern "C" void kernel_launch(void* const* d_in, const int* in_sizes, int n_in,
                              void* d_out, int out_size) {
  const float* x    = (const float*)d_in[0];
  const float* ctx  = (const float*)d_in[1];
  const int*   mask = (const int*)d_in[2];
  const float* Wq   = (const float*)d_in[3];
  const float* bq   = (const float*)d_in[4];
  const float* Wk   = (const float*)d_in[5];
  const float* bk   = (const float*)d_in[6];
  const float* Wv   = (const float*)d_in[7];
  const float* bv   = (const float*)d_in[8];
  const float* Wo   = (const float*)d_in[9];
  const float* bo   = (const float*)d_in[10];
  float* out = (float*)d_out;

  float *p, *q, *k, *v;
  cudaGetSymbolAddress((void**)&p, g_p);
  cudaGetSymbolAddress((void**)&q, g_q);
  cudaGetSymbolAddress((void**)&k, g_k);
  cudaGetSymbolAddress((void**)&v, g_v);

  cudaFuncSetAttribute(attn_mma, cudaFuncAttributeMaxDynamicSharedMemorySize,
                       ATT_SMEM);

  dim3 gg(TT / 128, CH / 128, BSZ);
  dim3 tg(TT / 64, BSZ * NH);
  dim3 ag(TT / 64, NH, BSZ);

  gemm_tf32<<<gg, 256>>>(Wq, x, bq, p);
  rope_transpose<<<tg, 256>>>(p, q, 1);
  gemm_tf32<<<gg, 256>>>(Wk, ctx, bk, p);
  rope_transpose<<<tg, 256>>>(p, k, 1);
  gemm_tf32<<<gg, 256>>>(Wv, ctx, bv, p);
  rope_transpose<<<tg, 256>>>(p, v, 0);
  attn_mma<<<ag, 128, ATT_SMEM>>>(q, k, v, mask, p);
  gemm_tf32<<<gg, 256>>>(Wo, p, bo, out);
}

// round 6
// speedup vs baseline: 4.3014x; 1.0408x over previous
#include <cuda_runtime.h>
#include <math.h>

#define BSZ 8
#define CH  1024
#define TT  1024
#define NH  16
#define HD  64
#define RD  32   // rope dim
#define RH  16   // rope half

// ---------------- scratch (device globals; no allocation allowed) ----------
__device__ float g_p[(size_t)BSZ * CH * TT];   // attn out (proj-input layout)
__device__ float g_q[(size_t)BSZ * CH * TT];   // [B,H,T,D]
__device__ float g_k[(size_t)BSZ * CH * TT];
__device__ float g_v[(size_t)BSZ * CH * TT];

// ---------------------------------------------------------------------------
__device__ __forceinline__ unsigned f2tf32(float x) {
  unsigned r;
  asm("cvt.rna.tf32.f32 %0, %1;" : "=r"(r) : "f"(x));
  return r;
}

__device__ __forceinline__ void mma_tf32(float c[4], unsigned a0, unsigned a1,
                                         unsigned a2, unsigned a3, unsigned b0,
                                         unsigned b1) {
  asm volatile(
      "mma.sync.aligned.m16n8k8.row.col.f32.tf32.tf32.f32 "
      "{%0,%1,%2,%3}, {%4,%5,%6,%7}, {%8,%9}, {%0,%1,%2,%3};"
      : "+f"(c[0]), "+f"(c[1]), "+f"(c[2]), "+f"(c[3])
      : "r"(a0), "r"(a1), "r"(a2), "r"(a3), "r"(b0), "r"(b1));
}

// ---------------------------------------------------------------------------
// TF32 tensor-core GEMM with register-prefetch double buffering.
//   acc[b][m][n] = sum_k W[m][k] * X[b][k][n] + bias[m]
// mode 0: Out[B,C,T] = acc                       (final projection)
// mode 1: Out[B,H,T,D] = rope(acc) (transposed)  (Q, K)
// mode 2: Out[B,H,T,D] = acc       (transposed)  (V)
// grid (T/128, C/128, B), 256 threads (8 warps, 2m x 4n), warp tile 64x32.
// ---------------------------------------------------------------------------
__global__ void __launch_bounds__(256) gemm_tf32(
    const float* __restrict__ W, const float* __restrict__ X,
    const float* __restrict__ bias, float* __restrict__ Out, int mode) {
  __shared__ unsigned As[128][36];
  __shared__ unsigned Bs[32][136];

  const float* Xb = X + (size_t)blockIdx.z * CH * TT;
  const int m0 = blockIdx.y * 128, n0 = blockIdx.x * 128;
  const int tid = threadIdx.x;
  const int warp = tid >> 5, lane = tid & 31;
  const int wm = warp & 1, wn = warp >> 1;
  const int g = lane >> 2, tg = lane & 3;

  const int am = tid >> 3;          // 0..31
  const int ak = (tid & 7) * 4;     // 0..28
  const int bk = tid >> 5;          // 0..7
  const int bn = (tid & 31) * 4;    // 0..124

  float acc[4][4][4];
#pragma unroll
  for (int i = 0; i < 4; i++)
#pragma unroll
    for (int j = 0; j < 4; j++)
#pragma unroll
      for (int r = 0; r < 4; r++) acc[i][j][r] = 0.0f;

  float4 wreg[4], xreg[4];
#pragma unroll
  for (int p = 0; p < 4; p++) {
    wreg[p] = *(const float4*)&W[(size_t)(m0 + p * 32 + am) * CH + ak];
    xreg[p] = *(const float4*)&Xb[(size_t)(p * 8 + bk) * TT + n0 + bn];
  }

  for (int k0 = 0; k0 < CH; k0 += 32) {
    // store prefetched regs -> smem (tf32)
#pragma unroll
    for (int p = 0; p < 4; p++) {
      int m = p * 32 + am;
      As[m][ak + 0] = f2tf32(wreg[p].x);
      As[m][ak + 1] = f2tf32(wreg[p].y);
      As[m][ak + 2] = f2tf32(wreg[p].z);
      As[m][ak + 3] = f2tf32(wreg[p].w);
      int k = p * 8 + bk;
      uint4 u;
      u.x = f2tf32(xreg[p].x); u.y = f2tf32(xreg[p].y);
      u.z = f2tf32(xreg[p].z); u.w = f2tf32(xreg[p].w);
      *(uint4*)&Bs[k][bn] = u;
    }
    __syncthreads();

    // prefetch next tile (overlaps with the MMA block below)
    if (k0 + 32 < CH) {
#pragma unroll
      for (int p = 0; p < 4; p++) {
        wreg[p] =
            *(const float4*)&W[(size_t)(m0 + p * 32 + am) * CH + k0 + 32 + ak];
        xreg[p] =
            *(const float4*)&Xb[(size_t)(k0 + 32 + p * 8 + bk) * TT + n0 + bn];
      }
    }

#pragma unroll
    for (int ks = 0; ks < 4; ks++) {
      const int kk = ks * 8;
      unsigned a[4][4], b[4][2];
#pragma unroll
      for (int mi = 0; mi < 4; mi++) {
        int row = wm * 64 + mi * 16 + g;
        a[mi][0] = As[row][kk + tg];
        a[mi][1] = As[row + 8][kk + tg];
        a[mi][2] = As[row][kk + tg + 4];
        a[mi][3] = As[row + 8][kk + tg + 4];
      }
#pragma unroll
      for (int ni = 0; ni < 4; ni++) {
        int col = wn * 32 + ni * 8 + g;
        b[ni][0] = Bs[kk + tg][col];
        b[ni][1] = Bs[kk + tg + 4][col];
      }
#pragma unroll
      for (int mi = 0; mi < 4; mi++)
#pragma unroll
        for (int ni = 0; ni < 4; ni++)
          mma_tf32(acc[mi][ni], a[mi][0], a[mi][1], a[mi][2], a[mi][3],
                   b[ni][0], b[ni][1]);
    }
    __syncthreads();
  }

  // ---- bias ----
#pragma unroll
  for (int mi = 0; mi < 4; mi++) {
    float bv0 = bias[m0 + wm * 64 + mi * 16 + g];
    float bv1 = bias[m0 + wm * 64 + mi * 16 + g + 8];
#pragma unroll
    for (int ni = 0; ni < 4; ni++) {
      acc[mi][ni][0] += bv0; acc[mi][ni][1] += bv0;
      acc[mi][ni][2] += bv1; acc[mi][ni][3] += bv1;
    }
  }

  if (mode == 0) {
    float* Ob = Out + (size_t)blockIdx.z * CH * TT;
#pragma unroll
    for (int mi = 0; mi < 4; mi++) {
      int row = m0 + wm * 64 + mi * 16 + g;
#pragma unroll
      for (int ni = 0; ni < 4; ni++) {
        int col = n0 + wn * 32 + ni * 8 + 2 * tg;
        *(float2*)&Ob[(size_t)row * TT + col] =
            make_float2(acc[mi][ni][0], acc[mi][ni][1]);
        *(float2*)&Ob[(size_t)(row + 8) * TT + col] =
            make_float2(acc[mi][ni][2], acc[mi][ni][3]);
      }
    }
    return;
  }

  // ---- fused RoPE (mode 1): pair (d, d+16) = (acc[0], acc[1]) rows ----
  if (mode == 1) {
    // theta for d = g and d = g+8 (both < 16)
    float th0 = powf(10000.0f, -(2.0f * g) / (float)RD);
    float th1 = powf(10000.0f, -(2.0f * (g + 8)) / (float)RD);
#pragma unroll
    for (int ni = 0; ni < 4; ni++) {
      int t0c = n0 + wn * 32 + ni * 8 + 2 * tg;
#pragma unroll
      for (int j = 0; j < 2; j++) {   // j: column t0c+j
        float t = (float)(t0c + j);
        float s, c;
        // pair A: d=g (acc[0][ni][j]) with d=g+16 (acc[1][ni][j])
        sincosf(t * th0, &s, &c);
        float x0 = acc[0][ni][j], x1 = acc[1][ni][j];
        acc[0][ni][j] = x0 * c - x1 * s;
        acc[1][ni][j] = x1 * c + x0 * s;
        // pair B: d=g+8 (acc[0][ni][2+j]) with d=g+24 (acc[1][ni][2+j])
        sincosf(t * th1, &s, &c);
        float y0 = acc[0][ni][2 + j], y1 = acc[1][ni][2 + j];
        acc[0][ni][2 + j] = y0 * c - y1 * s;
        acc[1][ni][2 + j] = y1 * c + y0 * s;
      }
    }
  }

  // ---- transposed write to [B,H,T,D] ----
  {
    int head = blockIdx.y * 2 + wm;
    float* Oq = Out + ((size_t)blockIdx.z * NH + head) * TT * 64;
#pragma unroll
    for (int mi = 0; mi < 4; mi++) {
      int d = mi * 16 + g;
#pragma unroll
      for (int ni = 0; ni < 4; ni++) {
        int t = n0 + wn * 32 + ni * 8 + 2 * tg;
        Oq[(size_t)t * 64 + d] = acc[mi][ni][0];
        Oq[(size_t)(t + 1) * 64 + d] = acc[mi][ni][1];
        Oq[(size_t)t * 64 + d + 8] = acc[mi][ni][2];
        Oq[(size_t)(t + 1) * 64 + d + 8] = acc[mi][ni][3];
      }
    }
  }
}

// ---------------------------------------------------------------------------
// Tensor-core flash attention (tf32 mma, 64 q-rows/CTA, 64-key tiles).
// Q,K,V: [B,H,T,D] fp32. AO: [B, h*64+d, T].
// grid (T/64, H, B), 128 threads (4 warps, warp = 16 q-rows).
// ---------------------------------------------------------------------------
#define ASTR 68
#define ATT_SMEM (3 * 64 * ASTR * 4 + 1024 * 4 + 64 * 4)

__global__ void __launch_bounds__(128) attn_mma(
    const float* __restrict__ Q, const float* __restrict__ K,
    const float* __restrict__ V, const int* __restrict__ mask,
    float* __restrict__ AO) {
  extern __shared__ char smraw[];
  unsigned* Ks = (unsigned*)smraw;            // [64][ASTR]
  unsigned* Vs = Ks + 64 * ASTR;              // [64][ASTR]
  unsigned* Ps = Vs + 64 * ASTR;              // [64][ASTR]
  float* bias_t = (float*)(Ps + 64 * ASTR);   // [1024]
  int* msk = (int*)(bias_t + 1024);           // [64]
  float* Od = (float*)Ks;                     // output staging reuse

  const int tid = threadIdx.x;
  const int warp = tid >> 5, lane = tid & 31;
  const int g = lane >> 2, tg = lane & 3;
  const int b = blockIdx.z, h = blockIdx.y, q0 = blockIdx.x * 64;
  const size_t bh = (size_t)b * NH + h;
  const float* Qb = Q + (bh * TT + q0) * 64;
  const float* Kb = K + bh * TT * 64;
  const float* Vb = V + bh * TT * 64;
  const int* mb = mask + (size_t)b * TT;

  for (int i = tid; i < 1024; i += 128) bias_t[i] = -log1pf((float)i);

#pragma unroll
  for (int i = 0; i < 8; i++) {
    int idx = i * 128 + tid;
    int row = idx >> 4, c4 = (idx & 15) * 4;
    float4 v4 = *(const float4*)&Qb[row * 64 + c4];
    uint4 u;
    u.x = f2tf32(v4.x * 0.125f); u.y = f2tf32(v4.y * 0.125f);
    u.z = f2tf32(v4.z * 0.125f); u.w = f2tf32(v4.w * 0.125f);
    *(uint4*)&Ps[row * ASTR + c4] = u;
  }
  __syncthreads();

  const int r0 = warp * 16 + g;
  unsigned aq[8][4];
#pragma unroll
  for (int kc = 0; kc < 8; kc++) {
    aq[kc][0] = Ps[r0 * ASTR + kc * 8 + tg];
    aq[kc][1] = Ps[(r0 + 8) * ASTR + kc * 8 + tg];
    aq[kc][2] = Ps[r0 * ASTR + kc * 8 + tg + 4];
    aq[kc][3] = Ps[(r0 + 8) * ASTR + kc * 8 + tg + 4];
  }

  float accO[8][4];
#pragma unroll
  for (int nt = 0; nt < 8; nt++)
#pragma unroll
    for (int i = 0; i < 4; i++) accO[nt][i] = 0.0f;
  float m0r = -INFINITY, m1r = -INFINITY, l0r = 0.0f, l1r = 0.0f;
  const int trow0 = q0 + r0, trow1 = trow0 + 8;

  for (int k0 = 0; k0 < TT; k0 += 64) {
    __syncthreads();
#pragma unroll
    for (int i = 0; i < 8; i++) {
      int idx = i * 128 + tid;
      int row = idx >> 4, c4 = (idx & 15) * 4;
      float4 kv = *(const float4*)&Kb[(size_t)(k0 + row) * 64 + c4];
      uint4 uk;
      uk.x = f2tf32(kv.x); uk.y = f2tf32(kv.y);
      uk.z = f2tf32(kv.z); uk.w = f2tf32(kv.w);
      *(uint4*)&Ks[row * ASTR + c4] = uk;
      float4 vv = *(const float4*)&Vb[(size_t)(k0 + row) * 64 + c4];
      uint4 uv;
      uv.x = f2tf32(vv.x); uv.y = f2tf32(vv.y);
      uv.z = f2tf32(vv.z); uv.w = f2tf32(vv.w);
      *(uint4*)&Vs[row * ASTR + c4] = uv;
    }
    if (tid < 64) msk[tid] = mb[k0 + tid];
    __syncthreads();

    float s[8][4];
#pragma unroll
    for (int nt = 0; nt < 8; nt++) {
      float c[4] = {0.0f, 0.0f, 0.0f, 0.0f};
#pragma unroll
      for (int kc = 0; kc < 8; kc++) {
        unsigned b0 = Ks[(nt * 8 + g) * ASTR + kc * 8 + tg];
        unsigned b1 = Ks[(nt * 8 + g) * ASTR + kc * 8 + tg + 4];
        mma_tf32(c, aq[kc][0], aq[kc][1], aq[kc][2], aq[kc][3], b0, b1);
      }
      int kl = nt * 8 + 2 * tg;
      int kA = k0 + kl;
      s[nt][0] = (msk[kl] == 0) ? -10000.0f : c[0] + bias_t[abs(trow0 - kA)];
      s[nt][1] = (msk[kl + 1] == 0) ? -10000.0f : c[1] + bias_t[abs(trow0 - kA - 1)];
      s[nt][2] = (msk[kl] == 0) ? -10000.0f : c[2] + bias_t[abs(trow1 - kA)];
      s[nt][3] = (msk[kl + 1] == 0) ? -10000.0f : c[3] + bias_t[abs(trow1 - kA - 1)];
    }

    float tm0 = -INFINITY, tm1 = -INFINITY;
#pragma unroll
    for (int nt = 0; nt < 8; nt++) {
      tm0 = fmaxf(tm0, fmaxf(s[nt][0], s[nt][1]));
      tm1 = fmaxf(tm1, fmaxf(s[nt][2], s[nt][3]));
    }
    tm0 = fmaxf(tm0, __shfl_xor_sync(0xffffffffu, tm0, 1));
    tm0 = fmaxf(tm0, __shfl_xor_sync(0xffffffffu, tm0, 2));
    tm1 = fmaxf(tm1, __shfl_xor_sync(0xffffffffu, tm1, 1));
    tm1 = fmaxf(tm1, __shfl_xor_sync(0xffffffffu, tm1, 2));
    float mn0 = fmaxf(m0r, tm0), mn1 = fmaxf(m1r, tm1);
    float sc0 = __expf(m0r - mn0), sc1 = __expf(m1r - mn1);
    m0r = mn0; m1r = mn1;

    float ps0 = 0.0f, ps1 = 0.0f;
#pragma unroll
    for (int nt = 0; nt < 8; nt++) {
      int col = nt * 8 + 2 * tg;
      float p0 = __expf(s[nt][0] - mn0);
      float p1 = __expf(s[nt][1] - mn0);
      float p2 = __expf(s[nt][2] - mn1);
      float p3 = __expf(s[nt][3] - mn1);
      ps0 += p0 + p1; ps1 += p2 + p3;
      Ps[r0 * ASTR + col] = f2tf32(p0);
      Ps[r0 * ASTR + col + 1] = f2tf32(p1);
      Ps[(r0 + 8) * ASTR + col] = f2tf32(p2);
      Ps[(r0 + 8) * ASTR + col + 1] = f2tf32(p3);
    }
    ps0 += __shfl_xor_sync(0xffffffffu, ps0, 1);
    ps0 += __shfl_xor_sync(0xffffffffu, ps0, 2);
    ps1 += __shfl_xor_sync(0xffffffffu, ps1, 1);
    ps1 += __shfl_xor_sync(0xffffffffu, ps1, 2);
    l0r = l0r * sc0 + ps0;
    l1r = l1r * sc1 + ps1;

#pragma unroll
    for (int nt = 0; nt < 8; nt++) {
      accO[nt][0] *= sc0; accO[nt][1] *= sc0;
      accO[nt][2] *= sc1; accO[nt][3] *= sc1;
    }

    __syncwarp();

#pragma unroll
    for (int kc = 0; kc < 8; kc++) {
      unsigned a0 = Ps[r0 * ASTR + kc * 8 + tg];
      unsigned a1 = Ps[(r0 + 8) * ASTR + kc * 8 + tg];
      unsigned a2 = Ps[r0 * ASTR + kc * 8 + tg + 4];
      unsigned a3 = Ps[(r0 + 8) * ASTR + kc * 8 + tg + 4];
#pragma unroll
      for (int nt = 0; nt < 8; nt++) {
        unsigned b0 = Vs[(kc * 8 + tg) * ASTR + nt * 8 + g];
        unsigned b1 = Vs[(kc * 8 + tg + 4) * ASTR + nt * 8 + g];
        mma_tf32(accO[nt], a0, a1, a2, a3, b0, b1);
      }
    }
  }

  __syncthreads();
  float inv0 = 1.0f / l0r, inv1 = 1.0f / l1r;
#pragma unroll
  for (int nt = 0; nt < 8; nt++) {
    int d = nt * 8 + 2 * tg;
    Od[d * ASTR + r0] = accO[nt][0] * inv0;
    Od[(d + 1) * ASTR + r0] = accO[nt][1] * inv0;
    Od[d * ASTR + r0 + 8] = accO[nt][2] * inv1;
    Od[(d + 1) * ASTR + r0 + 8] = accO[nt][3] * inv1;
  }
  __syncthreads();
  {
    int d = tid >> 1;
    int c0 = (tid & 1) * 32;
    float* ao = AO + ((size_t)b * CH + (size_t)h * 64 + d) * TT + q0 + c0;
#pragma unroll
    for (int i = 0; i < 8; i++) {
      float4 o4 = *(float4*)&Od[d * ASTR + c0 + i * 4];
      *(float4*)&ao[i * 4] = o4;
    }
  }
}

// ---------------------------------------------------------------------------
extern "C" void kernel_launch(void* const* d_in, const int* in_sizes, int n_in,
                              void* d_out, int out_size) {
  const float* x    = (const float*)d_in[0];
  const float* ctx  = (const float*)d_in[1];
  const int*   mask = (const int*)d_in[2];
  const float* Wq   = (const float*)d_in[3];
  const float* bq   = (const float*)d_in[4];
  const float* Wk   = (const float*)d_in[5];
  const float* bk   = (const float*)d_in[6];
  const float* Wv   = (const float*)d_in[7];
  const float* bv   = (const float*)d_in[8];
  const float* Wo   = (const float*)d_in[9];
  const float* bo   = (const float*)d_in[10];
  float* out = (float*)d_out;

  float *p, *q, *k, *v;
  cudaGetSymbolAddress((void**)&p, g_p);
  cudaGetSymbolAddress((void**)&q, g_q);
  cudaGetSymbolAddress((void**)&k, g_k);
  cudaGetSymbolAddress((void**)&v, g_v);

  cudaFuncSetAttribute(attn_mma, cudaFuncAttributeMaxDynamicSharedMemorySize,
                       ATT_SMEM);

  dim3 gg(TT / 128, CH / 128, BSZ);
  dim3 ag(TT / 64, NH, BSZ);

  gemm_tf32<<<gg, 256>>>(Wq, x, bq, q, 1);     // Q proj + rope + transpose
  gemm_tf32<<<gg, 256>>>(Wk, ctx, bk, k, 1);   // K proj + rope + transpose
  gemm_tf32<<<gg, 256>>>(Wv, ctx, bv, v, 2);   // V proj + transpose
  attn_mma<<<ag, 128, ATT_SMEM>>>(q, k, v, mask, p);
  gemm_tf32<<<gg, 256>>>(Wo, p, bo, out, 0);   // output projection
}